// round 8
// baseline (speedup 1.0000x reference)
#include <cuda_runtime.h>
#include <cuda_bf16.h>
#include <cstdint>

#define D        128
#define N1       81920
#define BATCH    8192
#define KNB      10
#define TM       128        // rows per block (M)
#define NTHREADS 512        // 8 MMA warps + 8 gather warps
#define KPAD     136        // padded k-stride in bf16 elems
#define ROWB     (KPAD * 2) // 272 bytes per row

// ---------------- device-global scratch (allocation-free rule) ----------------
__device__ float g_h1[(size_t)N1 * D];                 // layer-1 embeddings

// ---------------- smem layout ----------------
#define OFF_A0H  0                        // self hi  [128][KPAD] bf16 = 34816 B
#define OFF_A0L  34816                    // self lo
#define OFF_A1H  69632                    // agg  hi
#define OFF_A1L  104448                   // agg  lo
#define OFF_BH   139264                   // W half hi [128 n][KPAD]
#define OFF_BL   174080                   // W half lo
#define SMEM_TOTAL 208896                 // ~204 KB

// ---------------- PTX helpers ----------------
__device__ __forceinline__ uint32_t smem_u32(const void* p) {
    uint32_t a;
    asm("{ .reg .u64 t; cvta.to.shared.u64 t, %1; cvt.u32.u64 %0, t; }"
        : "=r"(a) : "l"(p));
    return a;
}
#define LDSM4(r, addr)                                                       \
    asm volatile("ldmatrix.sync.aligned.m8n8.x4.shared.b16 {%0,%1,%2,%3}, [%4];" \
                 : "=r"((r)[0]), "=r"((r)[1]), "=r"((r)[2]), "=r"((r)[3])    \
                 : "r"(addr))
#define MMA16816(c, a, b0, b1)                                               \
    asm volatile("mma.sync.aligned.m16n8k16.row.col.f32.bf16.bf16.f32 "      \
                 "{%0,%1,%2,%3}, {%4,%5,%6,%7}, {%8,%9}, {%0,%1,%2,%3};"     \
                 : "+f"((c)[0]), "+f"((c)[1]), "+f"((c)[2]), "+f"((c)[3])    \
                 : "r"((a)[0]), "r"((a)[1]), "r"((a)[2]), "r"((a)[3]),       \
                   "r"(b0), "r"(b1))
#define BAR_SYNC(id, cnt) \
    asm volatile("bar.sync %0, %1;" :: "r"(id), "r"(cnt) : "memory")
#define BAR_ARRIVE(id, cnt) \
    asm volatile("bar.arrive %0, %1;" :: "r"(id), "r"(cnt) : "memory")

__device__ __forceinline__ uint32_t pack_bf2(float a, float b) {
    __nv_bfloat16 ha = __float2bfloat16_rn(a), hb = __float2bfloat16_rn(b);
    return (uint32_t)__bfloat16_as_ushort(ha) |
           ((uint32_t)__bfloat16_as_ushort(hb) << 16);
}
// split float4 into bf16 hi + bf16 residual lo; 8-B store each
__device__ __forceinline__ void split_store(char* hi_p, char* lo_p, float4 v) {
    __nv_bfloat16 hx = __float2bfloat16_rn(v.x), hy = __float2bfloat16_rn(v.y);
    __nv_bfloat16 hz = __float2bfloat16_rn(v.z), hw = __float2bfloat16_rn(v.w);
    uint2 hv, lv;
    hv.x = (uint32_t)__bfloat16_as_ushort(hx) | ((uint32_t)__bfloat16_as_ushort(hy) << 16);
    hv.y = (uint32_t)__bfloat16_as_ushort(hz) | ((uint32_t)__bfloat16_as_ushort(hw) << 16);
    lv.x = pack_bf2(v.x - __bfloat162float(hx), v.y - __bfloat162float(hy));
    lv.y = pack_bf2(v.z - __bfloat162float(hz), v.w - __bfloat162float(hw));
    *(uint2*)hi_p = hv;
    *(uint2*)lo_p = lv;
}

// stage one K=128 phase of W (fp32, [n=128][d=256]) into BH/BL, split hi/lo.
// executed by the 256 MMA threads (tm = 0..255).
__device__ __forceinline__ void stage_B(const float* __restrict__ W, int phase,
                                        char* smem, int tm) {
    const int j    = tm >> 1;
    const int half = tm & 1;
    const float4* src = (const float4*)(W + j * 256 + phase * 128 + half * 64);
    char* hp = smem + OFF_BH + j * ROWB + half * 128;
    char* lp = smem + OFF_BL + j * ROWB + half * 128;
    #pragma unroll
    for (int i = 0; i < 16; i++) {
        float4 v = src[i];
        split_store(hp + i * 8, lp + i * 8, v);
    }
}

// one K=128 phase of the split GEMM: acc += Ah*Bh + Al*Bh + Ah*Bl
__device__ __forceinline__ void mma_phase(uint32_t aH, uint32_t aL,
                                          uint32_t bH, uint32_t bL,
                                          int lane, float acc[2][8][4]) {
    const uint32_t pa = (uint32_t)((lane & 15) * ROWB + (lane >> 4) * 16);
    const uint32_t pb = (uint32_t)(((lane & 7) + ((lane >> 4) << 3)) * ROWB +
                                   ((lane >> 3) & 1) * 16);
    #pragma unroll
    for (int ks = 0; ks < 8; ks++) {
        const uint32_t ko = ks * 32;
        uint32_t ah[2][4], al[2][4];
        #pragma unroll
        for (int mt = 0; mt < 2; mt++) {
            LDSM4(ah[mt], aH + pa + mt * 16 * ROWB + ko);
            LDSM4(al[mt], aL + pa + mt * 16 * ROWB + ko);
        }
        #pragma unroll
        for (int nq = 0; nq < 4; nq++) {
            uint32_t bh[4], bl[4];
            LDSM4(bh, bH + pb + nq * 16 * ROWB + ko);
            LDSM4(bl, bL + pb + nq * 16 * ROWB + ko);
            #pragma unroll
            for (int mt = 0; mt < 2; mt++) {
                MMA16816(acc[mt][nq * 2 + 0], ah[mt], bh[0], bh[1]);
                MMA16816(acc[mt][nq * 2 + 1], ah[mt], bh[2], bh[3]);
                MMA16816(acc[mt][nq * 2 + 0], al[mt], bh[0], bh[1]);
                MMA16816(acc[mt][nq * 2 + 1], al[mt], bh[2], bh[3]);
                MMA16816(acc[mt][nq * 2 + 0], ah[mt], bl[0], bl[1]);
                MMA16816(acc[mt][nq * 2 + 1], ah[mt], bl[2], bl[3]);
            }
        }
    }
}

// ---------------- fused SAGE layer, warp-specialized -------------------------
// warps 0-7:  MMA consumers (stage B, run split-GEMM, epilogue)
// warps 8-15: gather producers (self -> A0, mean-agg -> A1)
// bar 1: A0 ready   bar 2: A1 ready   bar 3: MMA-warp internal (B reuse)
template <int LAYER>
__global__ __launch_bounds__(NTHREADS, 1)
void sage_mma_kernel(const float* __restrict__ feats_in,
                     const float* __restrict__ Wg,
                     const int*   __restrict__ self_idx,
                     const int*   __restrict__ neigh_idx,
                     float*       __restrict__ out_ext) {
    extern __shared__ char smem[];
    const uint32_t sb = smem_u32(smem);
    const int t = threadIdx.x, lane = t & 31, wid = t >> 5;

    const float* feats = (LAYER == 1) ? feats_in : g_h1;
    float*       out   = (LAYER == 1) ? g_h1 : out_ext;

    if (wid >= 8) {
        // ================= gather producers =================
        const int gw = wid - 8;                  // 0..7, 16 rows each
        // ---- pass 1: self features -> A0 (1 load per row) ----
        #pragma unroll 4
        for (int rr = 0; rr < 16; rr++) {
            const int r    = gw * 16 + rr;
            const int row  = blockIdx.x * TM + r;
            const int nsel = __ldg(&self_idx[row]);
            float4 s = __ldg((const float4*)&feats[(size_t)nsel * D] + lane);
            const int so = r * ROWB + lane * 8;
            split_store(smem + OFF_A0H + so, smem + OFF_A0L + so, s);
        }
        __threadfence_block();
        BAR_ARRIVE(1, NTHREADS);

        // ---- pass 2: mean aggregate -> A1 (10 loads per row) ----
        #pragma unroll 2
        for (int rr = 0; rr < 16; rr++) {
            const int r   = gw * 16 + rr;
            const int row = blockIdx.x * TM + r;
            float4 a = make_float4(0.f, 0.f, 0.f, 0.f);
            #pragma unroll
            for (int k = 0; k < KNB; k++) {
                const int nk = __ldg(&neigh_idx[row * KNB + k]);
                float4 f = __ldg((const float4*)&feats[(size_t)nk * D] + lane);
                a.x += f.x; a.y += f.y; a.z += f.z; a.w += f.w;
            }
            const float inv = 1.0f / (float)KNB;
            a.x *= inv; a.y *= inv; a.z *= inv; a.w *= inv;
            const int so = r * ROWB + lane * 8;
            split_store(smem + OFF_A1H + so, smem + OFF_A1L + so, a);
        }
        __threadfence_block();
        BAR_ARRIVE(2, NTHREADS);
    } else {
        // ================= MMA consumers =================
        const int wm = wid & 3, wn = wid >> 2;   // 4(m) x 2(n) warp tiling
        const uint32_t aoff = (uint32_t)(wm * 32 * ROWB);
        const uint32_t boff = (uint32_t)(wn * 64 * ROWB);

        float acc[2][8][4];
        #pragma unroll
        for (int mt = 0; mt < 2; mt++)
            #pragma unroll
            for (int nt = 0; nt < 8; nt++)
                #pragma unroll
                for (int c = 0; c < 4; c++) acc[mt][nt][c] = 0.0f;

        // stage B phase 0 (overlaps gather pass 1)
        stage_B(Wg, 0, smem, t);
        BAR_SYNC(3, 256);                        // B0 visible to all MMA warps
        BAR_SYNC(1, NTHREADS);                   // A0 ready

        mma_phase(sb + OFF_A0H + aoff, sb + OFF_A0L + aoff,
                  sb + OFF_BH + boff,  sb + OFF_BL + boff, lane, acc);

        BAR_SYNC(3, 256);                        // all MMA warps done reading B0
        stage_B(Wg, 1, smem, t);                 // overlaps tail of agg gather
        BAR_SYNC(3, 256);                        // B1 visible
        BAR_SYNC(2, NTHREADS);                   // A1 ready

        mma_phase(sb + OFF_A1H + aoff, sb + OFF_A1L + aoff,
                  sb + OFF_BH + boff,  sb + OFF_BL + boff, lane, acc);

        // ---- epilogue: ReLU + float2 stores ----
        const int rb = blockIdx.x * TM + wm * 32 + (lane >> 2);
        const int cb = wn * 64 + (lane & 3) * 2;
        #pragma unroll
        for (int mt = 0; mt < 2; mt++)
            #pragma unroll
            for (int nt = 0; nt < 8; nt++) {
                const int row = rb + mt * 16;
                const int col = cb + nt * 8;
                float2 v0 = make_float2(fmaxf(acc[mt][nt][0], 0.f),
                                        fmaxf(acc[mt][nt][1], 0.f));
                float2 v1 = make_float2(fmaxf(acc[mt][nt][2], 0.f),
                                        fmaxf(acc[mt][nt][3], 0.f));
                *(float2*)&out[(size_t)row * D + col]       = v0;
                *(float2*)&out[(size_t)(row + 8) * D + col] = v1;
            }
    }
}

// ---------------- launch ----------------
extern "C" void kernel_launch(void* const* d_in, const int* in_sizes, int n_in,
                              void* d_out, int out_size) {
    const float* raw_features = (const float*)d_in[0];
    const float* W1           = (const float*)d_in[1];
    const float* W2           = (const float*)d_in[2];
    const int*   layer1_nodes = (const int*)d_in[3];
    const int*   neigh0_idx   = (const int*)d_in[4];
    const int*   map_batch    = (const int*)d_in[5];
    const int*   neigh1_idx   = (const int*)d_in[6];
    float*       out          = (float*)d_out;

    cudaFuncSetAttribute(sage_mma_kernel<1>,
                         cudaFuncAttributeMaxDynamicSharedMemorySize, SMEM_TOTAL);
    cudaFuncSetAttribute(sage_mma_kernel<2>,
                         cudaFuncAttributeMaxDynamicSharedMemorySize, SMEM_TOTAL);

    sage_mma_kernel<1><<<N1 / TM, NTHREADS, SMEM_TOTAL>>>(
        raw_features, W1, layer1_nodes, neigh0_idx, nullptr);
    sage_mma_kernel<2><<<BATCH / TM, NTHREADS, SMEM_TOTAL>>>(
        nullptr, W2, map_batch, neigh1_idx, out);
}